// round 2
// baseline (speedup 1.0000x reference)
#include <cuda_runtime.h>
#include <math.h>

#define NPT 1024      // N tokens
#define CS_ 384
#define CZ_ 128
#define H_ 8
#define G_ 16
#define C_ 48
#define PV_ 12
#define CZ4_ 32
#define NSQ (NPT*NPT)

// ---------------- device scratch (no allocations allowed) ----------------
__device__ float g_qh  [NPT*H_*C_];     // rotated+scaled q  (n, h, 48)
__device__ float g_krot[NPT*H_*C_];     // rotated k         (n, h, 48)
__device__ float g_v   [NPT*H_*C_];     // v                 (n, h, 48)
__device__ float g_vpts[NPT*H_*PV_*3];  // v points          (n, h, p, coord)
__device__ float g_a   [H_*NSQ];        // attention logits/probs (h, n, m)
__device__ float g_zbar[NPT*H_*CZ_];    // sum_m a*z          (n, h, 128)
__device__ float g_feats[NPT*1024];     // concat features    (n, 1024)

// ---------------- K1: projections (q,k,v,v_pts) + rotation -----------------
// grid 128 blocks x 256 threads, 8 token rows per block.
__global__ void k_proj(const float* __restrict__ s, const float* __restrict__ rot,
                       const float* __restrict__ wq, const float* __restrict__ bq,
                       const float* __restrict__ wkv, const float* __restrict__ bkv,
                       const float* __restrict__ wkvp, const float* __restrict__ bkvp,
                       const float* __restrict__ gw)
{
    __shared__ float s_sm[8][CS_];
    __shared__ float qraw[8][CS_];
    __shared__ float kraw[8][CS_];
    __shared__ float rot_sm[8][9];
    __shared__ float hw_sm[G_];
    const int t  = threadIdx.x;
    const int n0 = blockIdx.x * 8;

    for (int e = t; e < 8*CS_; e += 256) ((float*)s_sm)[e] = s[n0*CS_ + e];
    for (int e = t; e < 72;     e += 256) ((float*)rot_sm)[e] = rot[n0*9 + e];
    if (t < G_) hw_sm[t] = 0.25f * log1pf(expf(gw[t])) * 0.57735026918962584f;
    __syncthreads();

    // 1440 useful output columns: 384 q | 768 kv | 288 v_pts. groups of 4.
    for (int gt = t; gt < 360; gt += 256) {
        const int c0 = gt * 4;
        float acc[4][8];
        #pragma unroll
        for (int j = 0; j < 4; j++)
            #pragma unroll
            for (int r = 0; r < 8; r++) acc[j][r] = 0.f;

        const float* w0; int stride; int cols[4];
        if (c0 < 384) {
            w0 = wq; stride = 384;
            #pragma unroll
            for (int j = 0; j < 4; j++) cols[j] = c0 + j;
        } else if (c0 < 1152) {
            w0 = wkv; stride = 768;
            #pragma unroll
            for (int j = 0; j < 4; j++) cols[j] = c0 - 384 + j;
        } else {
            w0 = wkvp; stride = 480;
            #pragma unroll
            for (int j = 0; j < 4; j++) {
                int tc = c0 - 1152 + j;
                int h = tc / 36, rr = tc % 36, p = rr / 3, cd = rr % 3;
                cols[j] = cd*160 + h*20 + 8 + p;   // v_pts columns of wkvp
            }
        }
        for (int k = 0; k < CS_; k++) {
            float wv[4];
            #pragma unroll
            for (int j = 0; j < 4; j++) wv[j] = w0[k*stride + cols[j]];
            #pragma unroll
            for (int r = 0; r < 8; r++) {
                float sv = s_sm[r][k];
                #pragma unroll
                for (int j = 0; j < 4; j++) acc[j][r] += sv * wv[j];
            }
        }
        #pragma unroll
        for (int j = 0; j < 4; j++) {
            int c = c0 + j;
            if (c < 384) {
                float b = bq[c];
                #pragma unroll
                for (int r = 0; r < 8; r++) qraw[r][c] = acc[j][r] + b;
            } else if (c < 1152) {
                int jj = c - 384; float b = bkv[jj];
                int h = jj / 96, rem = jj % 96;
                if (rem < 48) {
                    #pragma unroll
                    for (int r = 0; r < 8; r++) kraw[r][h*48 + rem] = acc[j][r] + b;
                } else {
                    #pragma unroll
                    for (int r = 0; r < 8; r++) g_v[(n0+r)*384 + h*48 + rem - 48] = acc[j][r] + b;
                }
            } else {
                int tc = c - 1152; float b = bkvp[cols[j]];
                #pragma unroll
                for (int r = 0; r < 8; r++) g_vpts[(n0+r)*288 + tc] = acc[j][r] + b;
            }
        }
    }
    __syncthreads();

    // rotation: qh = hw[g]/sqrt3 * R q ; krot = R k   (6144 scalar outputs)
    for (int task = t; task < 6144; task += 256) {
        int r = task / 768, rem = task % 768;
        int isK = rem >= 384;
        int e = isK ? rem - 384 : rem;
        int h = e / 48, g = (e % 48) / 3, i = e % 3;
        const float* src = isK ? &kraw[r][0] : &qraw[r][0];
        float v0 = src[h*48 + g*3 + 0];
        float v1 = src[h*48 + g*3 + 1];
        float v2 = src[h*48 + g*3 + 2];
        float val = rot_sm[r][i*3+0]*v0 + rot_sm[r][i*3+1]*v1 + rot_sm[r][i*3+2]*v2;
        if (isK) g_krot[(n0+r)*384 + e] = val;
        else     g_qh  [(n0+r)*384 + e] = val * hw_sm[g];
    }
}

// ---------------- K2a: qk logits  a[h,n,m] = qh[n,h,:].krot[m,h,:] ----------
__global__ void k_qk()
{
    const int h  = blockIdx.z;
    const int n0 = blockIdx.y * 64;
    const int m0 = blockIdx.x * 64;
    __shared__ float qs[64][49];
    __shared__ float ks[64][49];
    const int t = threadIdx.x;
    for (int e = t; e < 64*48; e += 256) {
        int r = e / 48, c = e % 48;
        qs[r][c] = g_qh  [(n0+r)*384 + h*48 + c];
        ks[r][c] = g_krot[(m0+r)*384 + h*48 + c];
    }
    __syncthreads();
    const int tx = t % 16, ty = t / 16;
    float acc[4][4] = {};
    for (int k = 0; k < 48; k++) {
        float aq[4], bk[4];
        #pragma unroll
        for (int i = 0; i < 4; i++) aq[i] = qs[ty*4+i][k];
        #pragma unroll
        for (int j = 0; j < 4; j++) bk[j] = ks[tx*4+j][k];
        #pragma unroll
        for (int i = 0; i < 4; i++)
            #pragma unroll
            for (int j = 0; j < 4; j++) acc[i][j] += aq[i] * bk[j];
    }
    #pragma unroll
    for (int i = 0; i < 4; i++)
        #pragma unroll
        for (int j = 0; j < 4; j++)
            g_a[h*NSQ + (n0+ty*4+i)*NPT + (m0+tx*4+j)] = acc[i][j];
}

// ---------------- K2b: stream z once, add sqrt(1/3)*(z.wb + bb) ------------
// grid (1024 n, 4 m-tiles) x 64 threads; each thread owns 4 m x 8 h.
__global__ void k_badd(const float* __restrict__ z, const float* __restrict__ wb,
                       const float* __restrict__ bb)
{
    __shared__ float z_sm[256*33];
    __shared__ float wb_sm[32*8];
    const int n  = blockIdx.x;
    const int m0 = blockIdx.y * 256;
    const int t  = threadIdx.x;
    float acc[4][8] = {};
    for (int cz0 = 0; cz0 < 128; cz0 += 32) {
        for (int e = t; e < 256*32; e += 64) {
            int row = e >> 5, c = e & 31;
            z_sm[row*33 + c] = z[(n*NPT + m0 + row)*128 + cz0 + c];
        }
        for (int e = t; e < 256; e += 64) wb_sm[e] = wb[(cz0 + (e>>3))*8 + (e&7)];
        __syncthreads();
        for (int c = 0; c < 32; c++) {
            float wbv[8];
            #pragma unroll
            for (int h = 0; h < 8; h++) wbv[h] = wb_sm[c*8 + h];
            #pragma unroll
            for (int i = 0; i < 4; i++) {
                float zv = z_sm[(t*4 + i)*33 + c];
                #pragma unroll
                for (int h = 0; h < 8; h++) acc[i][h] += zv * wbv[h];
            }
        }
        __syncthreads();
    }
    #pragma unroll
    for (int i = 0; i < 4; i++) {
        int m = m0 + t*4 + i;
        #pragma unroll
        for (int h = 0; h < 8; h++)
            g_a[h*NSQ + n*NPT + m] += 0.57735026918962584f * (acc[i][h] + bb[h]);
    }
}

// ---------------- K3: masked softmax over m -----------------
__global__ void k_softmax(const float* __restrict__ mask)
{
    const int bid = blockIdx.x;
    const int h = bid >> 10, n = bid & 1023;
    float* row = g_a + (size_t)h*NSQ + (size_t)n*NPT;
    const int t = threadIdx.x;
    const float mn = mask[n];
    float x[4]; float mx = -1e30f;
    #pragma unroll
    for (int j = 0; j < 4; j++) {
        int m = t + j*256;
        float xx = row[m] + 100000.0f * (mn * mask[m] - 1.0f);
        x[j] = xx; mx = fmaxf(mx, xx);
    }
    __shared__ float red[8];
    for (int o = 16; o; o >>= 1) mx = fmaxf(mx, __shfl_xor_sync(0xffffffffu, mx, o));
    if ((t & 31) == 0) red[t >> 5] = mx;
    __syncthreads();
    if (t == 0) { float r = red[0]; for (int w = 1; w < 8; w++) r = fmaxf(r, red[w]); red[0] = r; }
    __syncthreads();
    mx = red[0];
    __syncthreads();
    float sum = 0.f;
    #pragma unroll
    for (int j = 0; j < 4; j++) { x[j] = expf(x[j] - mx); sum += x[j]; }
    for (int o = 16; o; o >>= 1) sum += __shfl_xor_sync(0xffffffffu, sum, o);
    if ((t & 31) == 0) red[t >> 5] = sum;
    __syncthreads();
    if (t == 0) { float r = 0.f; for (int w = 0; w < 8; w++) r += red[w]; red[0] = r; }
    __syncthreads();
    const float inv = 1.0f / red[0];
    #pragma unroll
    for (int j = 0; j < 4; j++) row[t + j*256] = x[j] * inv;
}

// ---------------- K4a: zbar[n,h,cz] = sum_m a[h,n,m]*z[n,m,cz] -------------
// grid 1024 x 64 threads; thread owns 4 h x 4 cz.
__global__ void k_zbar(const float* __restrict__ z)
{
    __shared__ __align__(16) float z_sm[16*128];
    __shared__ float a_sm[8*16];
    const int n = blockIdx.x;
    const int t = threadIdx.x;
    const int hg  = t & 1;    // 2 groups of 4 heads
    const int czg = t >> 1;   // 32 groups of 4 cz
    float acc[4][4] = {};
    for (int m0 = 0; m0 < NPT; m0 += 16) {
        for (int e = t; e < 2048; e += 64)
            z_sm[e] = z[(n*NPT + m0 + (e >> 7))*128 + (e & 127)];
        for (int e = t; e < 128; e += 64)
            a_sm[e] = g_a[(e >> 4)*NSQ + n*NPT + m0 + (e & 15)];
        __syncthreads();
        for (int mm = 0; mm < 16; mm++) {
            float4 zv = *reinterpret_cast<const float4*>(&z_sm[mm*128 + czg*4]);
            float av[4];
            #pragma unroll
            for (int hi = 0; hi < 4; hi++) av[hi] = a_sm[(hg*4 + hi)*16 + mm];
            #pragma unroll
            for (int hi = 0; hi < 4; hi++) {
                acc[hi][0] += av[hi]*zv.x; acc[hi][1] += av[hi]*zv.y;
                acc[hi][2] += av[hi]*zv.z; acc[hi][3] += av[hi]*zv.w;
            }
        }
        __syncthreads();
    }
    #pragma unroll
    for (int hi = 0; hi < 4; hi++)
        #pragma unroll
        for (int ci = 0; ci < 4; ci++)
            g_zbar[n*1024 + (hg*4 + hi)*128 + czg*4 + ci] = acc[hi][ci];
}

// ---------------- K4b: o and o_pt = A @ [v | v_pts] per head ----------------
// grid (64 n-tiles, 8 h) x 96 threads; 16 rows x 96 cols (84 valid) per block.
__global__ void k_ov()
{
    __shared__ float a_sm[16*33];
    __shared__ __align__(16) float vv_sm[32*100];
    const int h  = blockIdx.y;
    const int n0 = blockIdx.x * 16;
    const int t  = threadIdx.x;           // 96
    const int rg = t / 24, cg = t % 24;   // 4x4 tile each
    float acc[4][4] = {};
    for (int m0 = 0; m0 < NPT; m0 += 32) {
        for (int e = t; e < 512; e += 96) {
            int r = e >> 5, mm = e & 31;
            a_sm[r*33 + mm] = g_a[h*NSQ + (n0 + r)*NPT + m0 + mm];
        }
        for (int e = t; e < 32*96; e += 96) {
            int mm = e / 96, c = e % 96;
            int m = m0 + mm;
            float val = 0.f;
            if (c < 48)       val = g_v[m*384 + h*48 + c];
            else if (c < 84)  val = g_vpts[m*288 + h*36 + (c - 48)];
            vv_sm[mm*100 + c] = val;
        }
        __syncthreads();
        for (int mm = 0; mm < 32; mm++) {
            float4 bv = *reinterpret_cast<const float4*>(&vv_sm[mm*100 + cg*4]);
            float av[4];
            #pragma unroll
            for (int i = 0; i < 4; i++) av[i] = a_sm[(rg*4 + i)*33 + mm];
            #pragma unroll
            for (int i = 0; i < 4; i++) {
                acc[i][0] += av[i]*bv.x; acc[i][1] += av[i]*bv.y;
                acc[i][2] += av[i]*bv.z; acc[i][3] += av[i]*bv.w;
            }
        }
        __syncthreads();
    }
    #pragma unroll
    for (int i = 0; i < 4; i++) {
        int n = n0 + rg*4 + i;
        #pragma unroll
        for (int j = 0; j < 4; j++) {
            int c = cg*4 + j;
            if (c < 48) {
                g_feats[n*1024 + h*48 + c] = acc[i][j];
            } else if (c < 84) {
                int p = (c - 48) / 3, coord = (c - 48) % 3;
                g_feats[n*1024 + 384 + coord*96 + h*12 + p] = acc[i][j];
            }
        }
    }
}

// ---------------- K5: o_pair = zbar@wdz + bdz, point norms ------------------
__global__ void k_pair_norm(const float* __restrict__ wdz, const float* __restrict__ bdz)
{
    __shared__ float zb[1024];
    const int n = blockIdx.x;
    const int t = threadIdx.x;  // 256
    for (int e = t; e < 1024; e += 256) zb[e] = g_zbar[n*1024 + e];
    __syncthreads();
    {
        const int h = t >> 5, d = t & 31;
        float acc = bdz[d];
        for (int cz = 0; cz < 128; cz++) acc += zb[h*128 + cz] * wdz[cz*32 + d];
        g_feats[n*1024 + 768 + t] = acc;
    }
    if (t < 96) {
        float x  = g_feats[n*1024 + 384 + t];
        float y  = g_feats[n*1024 + 480 + t];
        float zz = g_feats[n*1024 + 576 + t];
        g_feats[n*1024 + 672 + t] = sqrtf(x*x + y*y + zz*zz + 1e-8f);
    }
}

// ---------------- K6: out = feats @ wout + bout -----------------------------
// grid (4 j-tiles, 32 n-tiles) x 256 threads; block 32 n x 96 j; thread 4x3.
__global__ void k_out(const float* __restrict__ wout, const float* __restrict__ bout,
                      float* __restrict__ out)
{
    __shared__ float f_sm[32*65];
    __shared__ float w_sm[64*97];
    const int n0 = blockIdx.y * 32;
    const int j0 = blockIdx.x * 96;
    const int t  = threadIdx.x;
    const int rg = t >> 5, cg = t & 31;
    float acc[4][3] = {};
    for (int e0 = 0; e0 < 1024; e0 += 64) {
        for (int e = t; e < 2048; e += 256) {
            int r = e >> 6, k = e & 63;
            f_sm[r*65 + k] = g_feats[(n0 + r)*1024 + e0 + k];
        }
        for (int e = t; e < 6144; e += 256) {
            int k = e / 96, c = e % 96;
            w_sm[k*97 + c] = wout[(e0 + k)*384 + j0 + c];
        }
        __syncthreads();
        for (int k = 0; k < 64; k++) {
            float av[4], bv[3];
            #pragma unroll
            for (int i = 0; i < 4; i++) av[i] = f_sm[(rg*4 + i)*65 + k];
            #pragma unroll
            for (int j = 0; j < 3; j++) bv[j] = w_sm[k*97 + cg*3 + j];
            #pragma unroll
            for (int i = 0; i < 4; i++)
                #pragma unroll
                for (int j = 0; j < 3; j++) acc[i][j] += av[i] * bv[j];
        }
        __syncthreads();
    }
    #pragma unroll
    for (int i = 0; i < 4; i++) {
        int n = n0 + rg*4 + i;
        #pragma unroll
        for (int j = 0; j < 3; j++) {
            int c = j0 + cg*3 + j;
            out[n*384 + c] = acc[i][j] + bout[c];
        }
    }
}

// ---------------- launch ----------------------------------------------------
extern "C" void kernel_launch(void* const* d_in, const int* in_sizes, int n_in,
                              void* d_out, int out_size)
{
    const float* s    = (const float*)d_in[0];
    const float* z    = (const float*)d_in[1];
    const float* rot  = (const float*)d_in[2];
    const float* mask = (const float*)d_in[3];
    const float* wq   = (const float*)d_in[4];
    const float* bq   = (const float*)d_in[5];
    const float* wkv  = (const float*)d_in[6];
    const float* bkv  = (const float*)d_in[7];
    const float* wkvp = (const float*)d_in[8];
    const float* bkvp = (const float*)d_in[9];
    const float* wb   = (const float*)d_in[10];
    const float* bb   = (const float*)d_in[11];
    const float* wdz  = (const float*)d_in[12];
    const float* bdz  = (const float*)d_in[13];
    const float* wout = (const float*)d_in[14];
    const float* bout = (const float*)d_in[15];
    const float* gw   = (const float*)d_in[16];
    float* out = (float*)d_out;

    k_proj<<<128, 256>>>(s, rot, wq, bq, wkv, bkv, wkvp, bkvp, gw);
    k_qk<<<dim3(16, 16, 8), 256>>>();
    k_badd<<<dim3(1024, 4), 64>>>(z, wb, bb);
    k_softmax<<<8192, 256>>>(mask);
    k_zbar<<<1024, 64>>>(z);
    k_ov<<<dim3(64, 8), 96>>>();
    k_pair_norm<<<1024, 256>>>(wdz, bdz);
    k_out<<<dim3(4, 32), 256>>>(wout, bout, out);
}

// round 3
// speedup vs baseline: 1.0004x; 1.0004x over previous
#include <cuda_runtime.h>
#include <math.h>

#define NPT 1024      // N tokens
#define CS_ 384
#define CZ_ 128
#define H_ 8
#define G_ 16
#define C_ 48
#define PV_ 12
#define CZ4_ 32
#define NSQ (NPT*NPT)

// ---------------- device scratch (no allocations allowed) ----------------
__device__ float g_qh  [NPT*H_*C_];     // rotated+scaled q  (n, h, 48)
__device__ float g_krot[NPT*H_*C_];     // rotated k         (n, h, 48)
__device__ float g_v   [NPT*H_*C_];     // v                 (n, h, 48)
__device__ float g_vpts[NPT*H_*PV_*3];  // v points          (n, h, p, coord)
__device__ float g_a   [H_*NSQ];        // attention logits/probs (h, n, m)
__device__ float g_zbar[NPT*H_*CZ_];    // sum_m a*z          (n, h, 128)
__device__ float g_feats[NPT*1024];     // concat features    (n, 1024)

// ---------------- K1: projections (q,k,v,v_pts) + rotation -----------------
// grid 128 blocks x 256 threads, 8 token rows per block.
__global__ void k_proj(const float* __restrict__ s, const float* __restrict__ rot,
                       const float* __restrict__ wq, const float* __restrict__ bq,
                       const float* __restrict__ wkv, const float* __restrict__ bkv,
                       const float* __restrict__ wkvp, const float* __restrict__ bkvp,
                       const float* __restrict__ gw)
{
    __shared__ float s_sm[8][CS_];
    __shared__ float qraw[8][CS_];
    __shared__ float kraw[8][CS_];
    __shared__ float rot_sm[8][9];
    __shared__ float hw_sm[G_];
    const int t  = threadIdx.x;
    const int n0 = blockIdx.x * 8;

    for (int e = t; e < 8*CS_; e += 256) ((float*)s_sm)[e] = s[n0*CS_ + e];
    for (int e = t; e < 72;     e += 256) ((float*)rot_sm)[e] = rot[n0*9 + e];
    if (t < G_) hw_sm[t] = 0.25f * log1pf(expf(gw[t])) * 0.57735026918962584f;
    __syncthreads();

    // 1440 useful output columns: 384 q | 768 kv | 288 v_pts. groups of 4.
    for (int gt = t; gt < 360; gt += 256) {
        const int c0 = gt * 4;
        float acc[4][8];
        #pragma unroll
        for (int j = 0; j < 4; j++)
            #pragma unroll
            for (int r = 0; r < 8; r++) acc[j][r] = 0.f;

        const float* w0; int stride; int cols[4];
        if (c0 < 384) {
            w0 = wq; stride = 384;
            #pragma unroll
            for (int j = 0; j < 4; j++) cols[j] = c0 + j;
        } else if (c0 < 1152) {
            w0 = wkv; stride = 768;
            #pragma unroll
            for (int j = 0; j < 4; j++) cols[j] = c0 - 384 + j;
        } else {
            w0 = wkvp; stride = 480;
            #pragma unroll
            for (int j = 0; j < 4; j++) {
                int tc = c0 - 1152 + j;
                int h = tc / 36, rr = tc % 36, p = rr / 3, cd = rr % 3;
                cols[j] = cd*160 + h*20 + 8 + p;   // v_pts columns of wkvp
            }
        }
        for (int k = 0; k < CS_; k++) {
            float wv[4];
            #pragma unroll
            for (int j = 0; j < 4; j++) wv[j] = w0[k*stride + cols[j]];
            #pragma unroll
            for (int r = 0; r < 8; r++) {
                float sv = s_sm[r][k];
                #pragma unroll
                for (int j = 0; j < 4; j++) acc[j][r] += sv * wv[j];
            }
        }
        #pragma unroll
        for (int j = 0; j < 4; j++) {
            int c = c0 + j;
            if (c < 384) {
                float b = bq[c];
                #pragma unroll
                for (int r = 0; r < 8; r++) qraw[r][c] = acc[j][r] + b;
            } else if (c < 1152) {
                int jj = c - 384; float b = bkv[jj];
                int h = jj / 96, rem = jj % 96;
                if (rem < 48) {
                    #pragma unroll
                    for (int r = 0; r < 8; r++) kraw[r][h*48 + rem] = acc[j][r] + b;
                } else {
                    #pragma unroll
                    for (int r = 0; r < 8; r++) g_v[(n0+r)*384 + h*48 + rem - 48] = acc[j][r] + b;
                }
            } else {
                int tc = c - 1152; float b = bkvp[cols[j]];
                #pragma unroll
                for (int r = 0; r < 8; r++) g_vpts[(n0+r)*288 + tc] = acc[j][r] + b;
            }
        }
    }
    __syncthreads();

    // rotation: qh = hw[g]/sqrt3 * R q ; krot = R k   (6144 scalar outputs)
    for (int task = t; task < 6144; task += 256) {
        int r = task / 768, rem = task % 768;
        int isK = rem >= 384;
        int e = isK ? rem - 384 : rem;
        int h = e / 48, g = (e % 48) / 3, i = e % 3;
        const float* src = isK ? &kraw[r][0] : &qraw[r][0];
        float v0 = src[h*48 + g*3 + 0];
        float v1 = src[h*48 + g*3 + 1];
        float v2 = src[h*48 + g*3 + 2];
        float val = rot_sm[r][i*3+0]*v0 + rot_sm[r][i*3+1]*v1 + rot_sm[r][i*3+2]*v2;
        if (isK) g_krot[(n0+r)*384 + e] = val;
        else     g_qh  [(n0+r)*384 + e] = val * hw_sm[g];
    }
}

// ---------------- K2a: qk logits  a[h,n,m] = qh[n,h,:].krot[m,h,:] ----------
__global__ void k_qk()
{
    const int h  = blockIdx.z;
    const int n0 = blockIdx.y * 64;
    const int m0 = blockIdx.x * 64;
    __shared__ float qs[64][49];
    __shared__ float ks[64][49];
    const int t = threadIdx.x;
    for (int e = t; e < 64*48; e += 256) {
        int r = e / 48, c = e % 48;
        qs[r][c] = g_qh  [(n0+r)*384 + h*48 + c];
        ks[r][c] = g_krot[(m0+r)*384 + h*48 + c];
    }
    __syncthreads();
    const int tx = t % 16, ty = t / 16;
    float acc[4][4] = {};
    for (int k = 0; k < 48; k++) {
        float aq[4], bk[4];
        #pragma unroll
        for (int i = 0; i < 4; i++) aq[i] = qs[ty*4+i][k];
        #pragma unroll
        for (int j = 0; j < 4; j++) bk[j] = ks[tx*4+j][k];
        #pragma unroll
        for (int i = 0; i < 4; i++)
            #pragma unroll
            for (int j = 0; j < 4; j++) acc[i][j] += aq[i] * bk[j];
    }
    #pragma unroll
    for (int i = 0; i < 4; i++)
        #pragma unroll
        for (int j = 0; j < 4; j++)
            g_a[h*NSQ + (n0+ty*4+i)*NPT + (m0+tx*4+j)] = acc[i][j];
}

// ---------------- K2b: stream z once, add sqrt(1/3)*(z.wb + bb) ------------
// grid (1024 n, 4 m-tiles) x 64 threads; each thread owns 4 m x 8 h.
__global__ void k_badd(const float* __restrict__ z, const float* __restrict__ wb,
                       const float* __restrict__ bb)
{
    __shared__ float z_sm[256*33];
    __shared__ float wb_sm[32*8];
    const int n  = blockIdx.x;
    const int m0 = blockIdx.y * 256;
    const int t  = threadIdx.x;
    float acc[4][8] = {};
    for (int cz0 = 0; cz0 < 128; cz0 += 32) {
        for (int e = t; e < 256*32; e += 64) {
            int row = e >> 5, c = e & 31;
            z_sm[row*33 + c] = z[(n*NPT + m0 + row)*128 + cz0 + c];
        }
        for (int e = t; e < 256; e += 64) wb_sm[e] = wb[(cz0 + (e>>3))*8 + (e&7)];
        __syncthreads();
        for (int c = 0; c < 32; c++) {
            float wbv[8];
            #pragma unroll
            for (int h = 0; h < 8; h++) wbv[h] = wb_sm[c*8 + h];
            #pragma unroll
            for (int i = 0; i < 4; i++) {
                float zv = z_sm[(t*4 + i)*33 + c];
                #pragma unroll
                for (int h = 0; h < 8; h++) acc[i][h] += zv * wbv[h];
            }
        }
        __syncthreads();
    }
    #pragma unroll
    for (int i = 0; i < 4; i++) {
        int m = m0 + t*4 + i;
        #pragma unroll
        for (int h = 0; h < 8; h++)
            g_a[h*NSQ + n*NPT + m] += 0.57735026918962584f * (acc[i][h] + bb[h]);
    }
}

// ---------------- K3: masked softmax over m -----------------
__global__ void k_softmax(const float* __restrict__ mask)
{
    const int bid = blockIdx.x;
    const int h = bid >> 10, n = bid & 1023;
    float* row = g_a + (size_t)h*NSQ + (size_t)n*NPT;
    const int t = threadIdx.x;
    const float mn = mask[n];
    float x[4]; float mx = -1e30f;
    #pragma unroll
    for (int j = 0; j < 4; j++) {
        int m = t + j*256;
        float xx = row[m] + 100000.0f * (mn * mask[m] - 1.0f);
        x[j] = xx; mx = fmaxf(mx, xx);
    }
    __shared__ float red[8];
    for (int o = 16; o; o >>= 1) mx = fmaxf(mx, __shfl_xor_sync(0xffffffffu, mx, o));
    if ((t & 31) == 0) red[t >> 5] = mx;
    __syncthreads();
    if (t == 0) { float r = red[0]; for (int w = 1; w < 8; w++) r = fmaxf(r, red[w]); red[0] = r; }
    __syncthreads();
    mx = red[0];
    __syncthreads();
    float sum = 0.f;
    #pragma unroll
    for (int j = 0; j < 4; j++) { x[j] = expf(x[j] - mx); sum += x[j]; }
    for (int o = 16; o; o >>= 1) sum += __shfl_xor_sync(0xffffffffu, sum, o);
    if ((t & 31) == 0) red[t >> 5] = sum;
    __syncthreads();
    if (t == 0) { float r = 0.f; for (int w = 0; w < 8; w++) r += red[w]; red[0] = r; }
    __syncthreads();
    const float inv = 1.0f / red[0];
    #pragma unroll
    for (int j = 0; j < 4; j++) row[t + j*256] = x[j] * inv;
}

// ---------------- K4a: zbar[n,h,cz] = sum_m a[h,n,m]*z[n,m,cz] -------------
// grid 1024 x 64 threads; thread owns 4 h x 4 cz.
__global__ void k_zbar(const float* __restrict__ z)
{
    __shared__ __align__(16) float z_sm[16*128];
    __shared__ float a_sm[8*16];
    const int n = blockIdx.x;
    const int t = threadIdx.x;
    const int hg  = t & 1;    // 2 groups of 4 heads
    const int czg = t >> 1;   // 32 groups of 4 cz
    float acc[4][4] = {};
    for (int m0 = 0; m0 < NPT; m0 += 16) {
        for (int e = t; e < 2048; e += 64)
            z_sm[e] = z[(n*NPT + m0 + (e >> 7))*128 + (e & 127)];
        for (int e = t; e < 128; e += 64)
            a_sm[e] = g_a[(e >> 4)*NSQ + n*NPT + m0 + (e & 15)];
        __syncthreads();
        for (int mm = 0; mm < 16; mm++) {
            float4 zv = *reinterpret_cast<const float4*>(&z_sm[mm*128 + czg*4]);
            float av[4];
            #pragma unroll
            for (int hi = 0; hi < 4; hi++) av[hi] = a_sm[(hg*4 + hi)*16 + mm];
            #pragma unroll
            for (int hi = 0; hi < 4; hi++) {
                acc[hi][0] += av[hi]*zv.x; acc[hi][1] += av[hi]*zv.y;
                acc[hi][2] += av[hi]*zv.z; acc[hi][3] += av[hi]*zv.w;
            }
        }
        __syncthreads();
    }
    #pragma unroll
    for (int hi = 0; hi < 4; hi++)
        #pragma unroll
        for (int ci = 0; ci < 4; ci++)
            g_zbar[n*1024 + (hg*4 + hi)*128 + czg*4 + ci] = acc[hi][ci];
}

// ---------------- K4b: o and o_pt = A @ [v | v_pts] per head ----------------
// grid (64 n-tiles, 8 h) x 96 threads; 16 rows x 96 cols (84 valid) per block.
__global__ void k_ov()
{
    __shared__ float a_sm[16*33];
    __shared__ __align__(16) float vv_sm[32*100];
    const int h  = blockIdx.y;
    const int n0 = blockIdx.x * 16;
    const int t  = threadIdx.x;           // 96
    const int rg = t / 24, cg = t % 24;   // 4x4 tile each
    float acc[4][4] = {};
    for (int m0 = 0; m0 < NPT; m0 += 32) {
        for (int e = t; e < 512; e += 96) {
            int r = e >> 5, mm = e & 31;
            a_sm[r*33 + mm] = g_a[h*NSQ + (n0 + r)*NPT + m0 + mm];
        }
        for (int e = t; e < 32*96; e += 96) {
            int mm = e / 96, c = e % 96;
            int m = m0 + mm;
            float val = 0.f;
            if (c < 48)       val = g_v[m*384 + h*48 + c];
            else if (c < 84)  val = g_vpts[m*288 + h*36 + (c - 48)];
            vv_sm[mm*100 + c] = val;
        }
        __syncthreads();
        for (int mm = 0; mm < 32; mm++) {
            float4 bv = *reinterpret_cast<const float4*>(&vv_sm[mm*100 + cg*4]);
            float av[4];
            #pragma unroll
            for (int i = 0; i < 4; i++) av[i] = a_sm[(rg*4 + i)*33 + mm];
            #pragma unroll
            for (int i = 0; i < 4; i++) {
                acc[i][0] += av[i]*bv.x; acc[i][1] += av[i]*bv.y;
                acc[i][2] += av[i]*bv.z; acc[i][3] += av[i]*bv.w;
            }
        }
        __syncthreads();
    }
    #pragma unroll
    for (int i = 0; i < 4; i++) {
        int n = n0 + rg*4 + i;
        #pragma unroll
        for (int j = 0; j < 4; j++) {
            int c = cg*4 + j;
            if (c < 48) {
                g_feats[n*1024 + h*48 + c] = acc[i][j];
            } else if (c < 84) {
                int p = (c - 48) / 3, coord = (c - 48) % 3;
                g_feats[n*1024 + 384 + coord*96 + h*12 + p] = acc[i][j];
            }
        }
    }
}

// ---------------- K5: o_pair = zbar@wdz + bdz, point norms ------------------
__global__ void k_pair_norm(const float* __restrict__ wdz, const float* __restrict__ bdz)
{
    __shared__ float zb[1024];
    const int n = blockIdx.x;
    const int t = threadIdx.x;  // 256
    for (int e = t; e < 1024; e += 256) zb[e] = g_zbar[n*1024 + e];
    __syncthreads();
    {
        const int h = t >> 5, d = t & 31;
        float acc = bdz[d];
        for (int cz = 0; cz < 128; cz++) acc += zb[h*128 + cz] * wdz[cz*32 + d];
        g_feats[n*1024 + 768 + t] = acc;
    }
    if (t < 96) {
        float x  = g_feats[n*1024 + 384 + t];
        float y  = g_feats[n*1024 + 480 + t];
        float zz = g_feats[n*1024 + 576 + t];
        g_feats[n*1024 + 672 + t] = sqrtf(x*x + y*y + zz*zz + 1e-8f);
    }
}

// ---------------- K6: out = feats @ wout + bout -----------------------------
// grid (4 j-tiles, 32 n-tiles) x 256 threads; block 32 n x 96 j; thread 4x3.
__global__ void k_out(const float* __restrict__ wout, const float* __restrict__ bout,
                      float* __restrict__ out)
{
    __shared__ float f_sm[32*65];
    __shared__ float w_sm[64*97];
    const int n0 = blockIdx.y * 32;
    const int j0 = blockIdx.x * 96;
    const int t  = threadIdx.x;
    const int rg = t >> 5, cg = t & 31;
    float acc[4][3] = {};
    for (int e0 = 0; e0 < 1024; e0 += 64) {
        for (int e = t; e < 2048; e += 256) {
            int r = e >> 6, k = e & 63;
            f_sm[r*65 + k] = g_feats[(n0 + r)*1024 + e0 + k];
        }
        for (int e = t; e < 6144; e += 256) {
            int k = e / 96, c = e % 96;
            w_sm[k*97 + c] = wout[(e0 + k)*384 + j0 + c];
        }
        __syncthreads();
        for (int k = 0; k < 64; k++) {
            float av[4], bv[3];
            #pragma unroll
            for (int i = 0; i < 4; i++) av[i] = f_sm[(rg*4 + i)*65 + k];
            #pragma unroll
            for (int j = 0; j < 3; j++) bv[j] = w_sm[k*97 + cg*3 + j];
            #pragma unroll
            for (int i = 0; i < 4; i++)
                #pragma unroll
                for (int j = 0; j < 3; j++) acc[i][j] += av[i] * bv[j];
        }
        __syncthreads();
    }
    #pragma unroll
    for (int i = 0; i < 4; i++) {
        int n = n0 + rg*4 + i;
        #pragma unroll
        for (int j = 0; j < 3; j++) {
            int c = j0 + cg*3 + j;
            out[n*384 + c] = acc[i][j] + bout[c];
        }
    }
}

// ---------------- launch ----------------------------------------------------
extern "C" void kernel_launch(void* const* d_in, const int* in_sizes, int n_in,
                              void* d_out, int out_size)
{
    const float* s    = (const float*)d_in[0];
    const float* z    = (const float*)d_in[1];
    const float* rot  = (const float*)d_in[2];
    const float* mask = (const float*)d_in[3];
    const float* wq   = (const float*)d_in[4];
    const float* bq   = (const float*)d_in[5];
    const float* wkv  = (const float*)d_in[6];
    const float* bkv  = (const float*)d_in[7];
    const float* wkvp = (const float*)d_in[8];
    const float* bkvp = (const float*)d_in[9];
    const float* wb   = (const float*)d_in[10];
    const float* bb   = (const float*)d_in[11];
    const float* wdz  = (const float*)d_in[12];
    const float* bdz  = (const float*)d_in[13];
    const float* wout = (const float*)d_in[14];
    const float* bout = (const float*)d_in[15];
    const float* gw   = (const float*)d_in[16];
    float* out = (float*)d_out;

    k_proj<<<128, 256>>>(s, rot, wq, bq, wkv, bkv, wkvp, bkvp, gw);
    k_qk<<<dim3(16, 16, 8), 256>>>();
    k_badd<<<dim3(1024, 4), 64>>>(z, wb, bb);
    k_softmax<<<8192, 256>>>(mask);
    k_zbar<<<1024, 64>>>(z);
    k_ov<<<dim3(64, 8), 96>>>();
    k_pair_norm<<<1024, 256>>>(wdz, bdz);
    k_out<<<dim3(4, 32), 256>>>(wout, bout, out);
}